// round 6
// baseline (speedup 1.0000x reference)
#include <cuda_runtime.h>
#include <math.h>

// ----------------------------------------------------------------------------
// FuncPitchEncoder: conv1d(1->10,k=12) + relu + maxpool4 -> [290] feat
//   -> fused fc+mu (290->128, W = mu_w@fc_w) -> VQ argmin over 64 codes
// Outputs: z = codebook[idx]  [BS,128], cmt_loss, perplexity
// ----------------------------------------------------------------------------

#define BS      131072
#define LEN     128
#define NCH     10
#define CONVK   12
#define POOLN   29          // pooled positions per channel
#define FEATN   290         // NCH * POOLN
#define EMB     256
#define ZD      128
#define KC_     64          // codebook size
#define ROWS    128         // rows per block
#define NBLK    (BS / ROWS) // 1024
#define THR     256

// fused-W GEMM chunking: 290 = 10 * 29
#define KCH     29
#define NCHUNK  10

// smem layout (floats)
#define FEATT_F   (FEATN * 132)            // 38280  featT[k][r], stride 132
#define REGA_F    8704                      // max(prs 32*132, wbuf 29*128, Ct 128*68)
#define OFF_REGA  FEATT_F
#define OFF_MISC  (FEATT_F + REGA_F)        // 46984
// misc: convw 120, convb 12, bf 128, cnorm 64, red 32  -> 356 floats
// ints: idx 128, counts 64 -> 192
#define SMEM_BYTES ((OFF_MISC + 356) * 4 + 192 * 4)

// ----------------------------- device scratch -------------------------------
__device__ float g_W[FEATN * ZD];      // [k][j]
__device__ float g_bf[ZD];
__device__ float g_cnorm[KC_];
__device__ float g_csum;
__device__ int   g_counts[KC_];
__device__ int   g_mask_u8;

// ----------------------------- setup kernel ---------------------------------
__global__ void setup_kernel(const float* __restrict__ fc_b,
                             const float* __restrict__ mu_w,
                             const float* __restrict__ mu_b,
                             const float* __restrict__ cb)
{
    int t = threadIdx.x;
    if (t == 0) { g_csum = 0.f; g_mask_u8 = 0; }
    if (t < KC_) g_counts[t] = 0;
    if (t < ZD) {
        float a = mu_b[t];
        for (int e = 0; e < EMB; e++) a = fmaf(mu_w[t * EMB + e], fc_b[e], a);
        g_bf[t] = a;
    }
    if (t >= 128 && t < 128 + KC_) {
        int k = t - 128;
        float a = 0.f;
        for (int z = 0; z < ZD; z++) { float c = cb[k * ZD + z]; a = fmaf(c, c, a); }
        g_cnorm[k] = a;
    }
}

// ------------------------- mask dtype detection -----------------------------
// If mask is int32 (values 0/1 LE), every byte at offset%4 != 0 is zero.
// If mask is uint8/bool, random 0/1 bytes appear at those offsets.
__global__ void detect_kernel(const unsigned char* __restrict__ m, int n)
{
    int i = blockIdx.x * blockDim.x + threadIdx.x;
    int f = 0;
    if (i < n && (i & 3)) f = (m[i] != 0);
    if (__any_sync(0xffffffffu, f)) {
        if ((threadIdx.x & 31) == 0) atomicOr(&g_mask_u8, 1);
    }
}

// ------------------------- fused-W precompute -------------------------------
// g_W[k][j] = sum_e mu_w[j][e] * fc_w[e][k]
__global__ void wfuse_kernel(const float* __restrict__ fc_w,
                             const float* __restrict__ mu_w)
{
    __shared__ float colw[EMB * 4];     // colw[e*4+kk] = fc_w[e][k0+kk]
    int t = threadIdx.x;                // 128 threads = j
    int k0 = blockIdx.x * 4;
    for (int i = t; i < EMB * 4; i += 128) {
        int e = i >> 2, kk = i & 3, k = k0 + kk;
        colw[i] = (k < FEATN) ? fc_w[e * FEATN + k] : 0.f;
    }
    __syncthreads();
    float a0 = 0.f, a1 = 0.f, a2 = 0.f, a3 = 0.f;
    const float* mr = mu_w + t * EMB;
    #pragma unroll 4
    for (int e = 0; e < EMB; e++) {
        float m = mr[e];
        a0 = fmaf(m, colw[e * 4 + 0], a0);
        a1 = fmaf(m, colw[e * 4 + 1], a1);
        a2 = fmaf(m, colw[e * 4 + 2], a2);
        a3 = fmaf(m, colw[e * 4 + 3], a3);
    }
    if (k0 + 0 < FEATN) g_W[(k0 + 0) * ZD + t] = a0;
    if (k0 + 1 < FEATN) g_W[(k0 + 1) * ZD + t] = a1;
    if (k0 + 2 < FEATN) g_W[(k0 + 2) * ZD + t] = a2;
    if (k0 + 3 < FEATN) g_W[(k0 + 3) * ZD + t] = a3;
}

// ------------------------------ main kernel ---------------------------------
__global__ __launch_bounds__(THR, 1)
void main_kernel(const float* __restrict__ pr,
                 const void*  __restrict__ mask,
                 const float* __restrict__ conv_w,
                 const float* __restrict__ conv_b,
                 const float* __restrict__ cb,
                 float* __restrict__ out)
{
    extern __shared__ float sm[];
    float* featT    = sm;                       // [290][132]  (phase3: mu_t [128][132])
    float* regA     = sm + OFF_REGA;            // prs / wbuf / Ct
    float* s_convw  = sm + OFF_MISC;            // 120
    float* s_convb  = s_convw + 120;            // 12
    float* s_bf     = s_convb + 12;             // 128
    float* s_cnorm  = s_bf + 128;               // 64
    float* s_red    = s_cnorm + 64;             // 32
    int*   s_idx    = (int*)(s_red + 32);       // 128
    int*   s_counts = s_idx + 128;              // 64

    const int t  = threadIdx.x;
    const int ty = t >> 4;                      // 0..15
    const int tx = t & 15;                      // 0..15
    const int blk = blockIdx.x;

    // ---- misc loads ----
    for (int i = t; i < 120; i += THR) s_convw[i] = conv_w[i];
    if (t < NCH)  s_convb[t] = conv_b[t];
    if (t < ZD)   s_bf[t]    = g_bf[t];
    if (t < KC_) { s_cnorm[t] = g_cnorm[t]; s_counts[t] = 0; }

    // =============== Phase 1: conv + relu + maxpool -> featT ===============
    float* prs = regA;                          // [32][132]
    for (int sub = 0; sub < 4; sub++) {
        int row0 = blk * ROWS + sub * 32;
        __syncthreads();                        // protect prs reuse + misc ready
        for (int i = t; i < 32 * LEN; i += THR) {
            int rr = i >> 7, c = i & 127;
            prs[rr * 132 + c] = pr[(row0 + rr) * LEN + c];
        }
        __syncthreads();
        for (int it = t; it < 32 * NCH; it += THR) {
            int rl = it / NCH, ch = it % NCH;
            int rloc = sub * 32 + rl;
            float wr[CONVK];
            #pragma unroll
            for (int i = 0; i < CONVK; i++) wr[i] = s_convw[ch * CONVK + i];
            float bb = s_convb[ch];
            const float* prow = &prs[rl * 132];
            float x[15];
            #pragma unroll
            for (int i = 0; i < 15; i++) x[i] = prow[i];
            #pragma unroll 1
            for (int p = 0; p < POOLN; p++) {
                float m = 0.f;                  // relu >= 0 so max starts at 0
                #pragma unroll
                for (int j = 0; j < 4; j++) {
                    float acc = bb;
                    #pragma unroll
                    for (int tt = 0; tt < CONVK; tt++)
                        acc = fmaf(x[j + tt], wr[tt], acc);
                    m = fmaxf(m, acc);
                }
                featT[(ch * POOLN + p) * 132 + rloc] = m;
                if (p < POOLN - 1) {
                    #pragma unroll
                    for (int i = 0; i < 11; i++) x[i] = x[i + 4];
                    #pragma unroll
                    for (int i = 0; i < 4; i++) x[11 + i] = prow[4 * p + 15 + i];
                }
            }
        }
    }
    __syncthreads();

    // =============== Phase 2: mu = featT^T @ W + b  (128x128x290) ==========
    float* wbuf = regA;                         // [29][128]
    const int r0 = ty * 8;
    const int j0 = tx * 8;
    float acc[64];
    #pragma unroll
    for (int i = 0; i < 64; i++) acc[i] = 0.f;

    for (int ck = 0; ck < NCHUNK; ck++) {
        for (int i = t; i < KCH * ZD; i += THR) wbuf[i] = g_W[ck * (KCH * ZD) + i];
        __syncthreads();
        #pragma unroll 4
        for (int kc = 0; kc < KCH; kc++) {
            const float* fa = &featT[(ck * KCH + kc) * 132 + r0];
            float4 a0 = *(const float4*)(fa);
            float4 a1 = *(const float4*)(fa + 4);
            const float* fb = &wbuf[kc * ZD + j0];
            float4 b0 = *(const float4*)(fb);
            float4 b1 = *(const float4*)(fb + 4);
            float av[8] = {a0.x, a0.y, a0.z, a0.w, a1.x, a1.y, a1.z, a1.w};
            float bv[8] = {b0.x, b0.y, b0.z, b0.w, b1.x, b1.y, b1.z, b1.w};
            #pragma unroll
            for (int ii = 0; ii < 8; ii++)
                #pragma unroll
                for (int jj = 0; jj < 8; jj++)
                    acc[ii * 8 + jj] = fmaf(av[ii], bv[jj], acc[ii * 8 + jj]);
        }
        __syncthreads();
    }

    // write mu transposed into featT region: mu_t[z][r], stride 132
    float* mu_t = featT;
    #pragma unroll
    for (int jj = 0; jj < 8; jj++) {
        float bias = s_bf[j0 + jj];
        #pragma unroll
        for (int ii = 0; ii < 8; ii++)
            mu_t[(j0 + jj) * 132 + (r0 + ii)] = acc[ii * 8 + jj] + bias;
    }

    // load codebook transposed: Ct[z][c], stride 68
    float* Ct = regA;
    for (int i = t; i < KC_ * ZD; i += THR) {
        int c = i >> 7, z = i & 127;            // coalesced gmem read
        Ct[z * 68 + c] = cb[i];
    }
    __syncthreads();

    // =============== Phase 3: scores = mu @ C^T (128x64x128) + argmin ======
    {
        const int c0 = tx * 4;
        float accp[32];
        #pragma unroll
        for (int i = 0; i < 32; i++) accp[i] = 0.f;
        #pragma unroll 4
        for (int z = 0; z < ZD; z++) {
            const float* fm = &mu_t[z * 132 + r0];
            float4 m0 = *(const float4*)(fm);
            float4 m1 = *(const float4*)(fm + 4);
            float4 cv = *(const float4*)(&Ct[z * 68 + c0]);
            float mv[8] = {m0.x, m0.y, m0.z, m0.w, m1.x, m1.y, m1.z, m1.w};
            float cvv[4] = {cv.x, cv.y, cv.z, cv.w};
            #pragma unroll
            for (int ii = 0; ii < 8; ii++)
                #pragma unroll
                for (int jj = 0; jj < 4; jj++)
                    accp[ii * 4 + jj] = fmaf(mv[ii], cvv[jj], accp[ii * 4 + jj]);
        }
        #pragma unroll
        for (int ii = 0; ii < 8; ii++) {
            float bv = 3.4e38f; int bi = 0;
            #pragma unroll
            for (int jj = 0; jj < 4; jj++) {
                float kv = s_cnorm[c0 + jj] - 2.f * accp[ii * 4 + jj];
                if (kv < bv) { bv = kv; bi = c0 + jj; }
            }
            #pragma unroll
            for (int o = 1; o < 16; o <<= 1) {
                float ov = __shfl_xor_sync(0xffffffffu, bv, o);
                int   oi = __shfl_xor_sync(0xffffffffu, bi, o);
                if (ov < bv || (ov == bv && oi < bi)) { bv = ov; bi = oi; }
            }
            if (tx == 0) s_idx[r0 + ii] = bi;
        }
    }
    __syncthreads();

    // =============== Phase 4: commitment, counts, z output =================
    const int flag_u8 = g_mask_u8;
    float cs = 0.f;
    int validrow = 0;
    if (t < ROWS) {
        int rg = blk * ROWS + t;
        validrow = flag_u8 ? (((const unsigned char*)mask)[rg] == 0)
                           : (((const int*)mask)[rg] == 0);
        int myidx = s_idx[t];
        #pragma unroll 4
        for (int z = 0; z < ZD; z++) {
            float d = Ct[z * 68 + myidx] - mu_t[z * 132 + t];
            cs = fmaf(d, d, cs);
        }
        if (validrow) atomicAdd(&s_counts[myidx], 1);
    }
    float v = (t < ROWS && validrow) ? cs : 0.f;
    #pragma unroll
    for (int o = 16; o > 0; o >>= 1) v += __shfl_down_sync(0xffffffffu, v, o);
    if ((t & 31) == 0) s_red[t >> 5] = v;
    __syncthreads();
    if (t == 0) {
        float tot = 0.f;
        for (int w = 0; w < 8; w++) tot += s_red[w];
        atomicAdd(&g_csum, tot);
    }
    if (t < KC_ && s_counts[t]) atomicAdd(&g_counts[t], s_counts[t]);

    // z = codebook[idx]
    long base = (long)blk * (ROWS * ZD);
    for (int i = t; i < ROWS * ZD; i += THR) {
        int r = i >> 7, z = i & 127;
        out[base + i] = cb[s_idx[r] * ZD + z];
    }
}

// ------------------------------ finalize ------------------------------------
__global__ void final_kernel(float* __restrict__ out)
{
    if (threadIdx.x == 0) {
        int nvi = 0;
        for (int k = 0; k < KC_; k++) nvi += g_counts[k];
        float nv = fmaxf((float)nvi, 1.f);
        float H = 0.f;
        for (int k = 0; k < KC_; k++) {
            float p = (float)g_counts[k] / nv;
            H += p * logf(p + 1e-10f);
        }
        out[(long)BS * ZD]     = 0.25f * g_csum / (nv * (float)ZD);
        out[(long)BS * ZD + 1] = expf(-H);
    }
}

// ------------------------------- launcher -----------------------------------
extern "C" void kernel_launch(void* const* d_in, const int* in_sizes, int n_in,
                              void* d_out, int out_size)
{
    const float* pr      = (const float*)d_in[0];
    const void*  mask    = d_in[1];
    const float* conv_w  = (const float*)d_in[2];
    const float* conv_b  = (const float*)d_in[3];
    const float* fc_w    = (const float*)d_in[4];
    const float* fc_b    = (const float*)d_in[5];
    const float* mu_w    = (const float*)d_in[6];
    const float* mu_b    = (const float*)d_in[7];
    const float* cb      = (const float*)d_in[8];
    float* out = (float*)d_out;

    cudaFuncSetAttribute(main_kernel,
                         cudaFuncAttributeMaxDynamicSharedMemorySize, SMEM_BYTES);

    setup_kernel<<<1, 256>>>(fc_b, mu_w, mu_b, cb);
    detect_kernel<<<(BS + 255) / 256, 256>>>((const unsigned char*)mask, BS);
    wfuse_kernel<<<(FEATN + 3) / 4, 128>>>(fc_w, mu_w);
    main_kernel<<<NBLK, THR, SMEM_BYTES>>>(pr, mask, conv_w, conv_b, cb, out);
    final_kernel<<<1, 32>>>(out);
}

// round 7
// speedup vs baseline: 1.8525x; 1.8525x over previous
#include <cuda_runtime.h>
#include <math.h>

// ----------------------------------------------------------------------------
// FuncPitchEncoder: conv1d(1->10,k=12) + relu + maxpool4 -> [290] feat
//   -> fused fc+mu (290->128, W = mu_w@fc_w) -> VQ argmin over 64 codes
// Outputs: z = codebook[idx]  [BS,128], cmt_loss, perplexity
// R6: 512 threads, K-split GEMM (2 groups x 8x8 tiles), full conv unroll,
//     double-buffered W loads.
// ----------------------------------------------------------------------------

#define BS      131072
#define LEN     128
#define NCH     10
#define CONVK   12
#define POOLN   29
#define FEATN   290
#define EMB     256
#define ZD      128
#define KC_     64
#define ROWS    128
#define NBLK    (BS / ROWS)
#define THR     512

#define KCH     29            // k per chunk
#define CHF     (KCH * ZD)    // 3712 floats per chunk
#define NPHASE  5             // chunks per K-group (2 groups x 5 = 10)

// smem layout (floats)
#define FEATT_F   (FEATN * 132)              // 38280: featT[k][r] stride 132
#define REGA_F    14848                      // prs 64*132=8448 | wbuf 2buf*2grp*3712 | Ct 128*68=8704
#define OFF_REGA  FEATT_F
#define OFF_MISC  (FEATT_F + REGA_F)         // 53128
#define PART_OFF  16896                      // partials inside featT region (after mu_t 128*132)
#define SMEM_BYTES ((OFF_MISC + 356) * 4 + 192 * 4)   // 214704 B

// ----------------------------- device scratch -------------------------------
__device__ __align__(16) float g_W[FEATN * ZD];   // [k][j]
__device__ float g_bf[ZD];
__device__ float g_cnorm[KC_];
__device__ float g_csum;
__device__ int   g_counts[KC_];
__device__ int   g_mask_u8;

// ----------------------------- setup kernel ---------------------------------
__global__ void setup_kernel(const float* __restrict__ fc_b,
                             const float* __restrict__ mu_w,
                             const float* __restrict__ mu_b,
                             const float* __restrict__ cb)
{
    int t = threadIdx.x;
    if (t == 0) { g_csum = 0.f; g_mask_u8 = 0; }
    if (t < KC_) g_counts[t] = 0;
    if (t < ZD) {
        float a = mu_b[t];
        for (int e = 0; e < EMB; e++) a = fmaf(mu_w[t * EMB + e], fc_b[e], a);
        g_bf[t] = a;
    }
    if (t >= 128 && t < 128 + KC_) {
        int k = t - 128;
        float a = 0.f;
        for (int z = 0; z < ZD; z++) { float c = cb[k * ZD + z]; a = fmaf(c, c, a); }
        g_cnorm[k] = a;
    }
}

// ------------------------- mask dtype detection -----------------------------
__global__ void detect_kernel(const unsigned char* __restrict__ m, int n)
{
    int i = blockIdx.x * blockDim.x + threadIdx.x;
    int f = 0;
    if (i < n && (i & 3)) f = (m[i] != 0);
    if (__any_sync(0xffffffffu, f)) {
        if ((threadIdx.x & 31) == 0) atomicOr(&g_mask_u8, 1);
    }
}

// ------------------------- fused-W precompute -------------------------------
__global__ void wfuse_kernel(const float* __restrict__ fc_w,
                             const float* __restrict__ mu_w)
{
    __shared__ float colw[EMB * 4];
    int t = threadIdx.x;
    int k0 = blockIdx.x * 4;
    for (int i = t; i < EMB * 4; i += 128) {
        int e = i >> 2, kk = i & 3, k = k0 + kk;
        colw[i] = (k < FEATN) ? fc_w[e * FEATN + k] : 0.f;
    }
    __syncthreads();
    float a0 = 0.f, a1 = 0.f, a2 = 0.f, a3 = 0.f;
    const float* mr = mu_w + t * EMB;
    #pragma unroll 4
    for (int e = 0; e < EMB; e++) {
        float m = mr[e];
        a0 = fmaf(m, colw[e * 4 + 0], a0);
        a1 = fmaf(m, colw[e * 4 + 1], a1);
        a2 = fmaf(m, colw[e * 4 + 2], a2);
        a3 = fmaf(m, colw[e * 4 + 3], a3);
    }
    if (k0 + 0 < FEATN) g_W[(k0 + 0) * ZD + t] = a0;
    if (k0 + 1 < FEATN) g_W[(k0 + 1) * ZD + t] = a1;
    if (k0 + 2 < FEATN) g_W[(k0 + 2) * ZD + t] = a2;
    if (k0 + 3 < FEATN) g_W[(k0 + 3) * ZD + t] = a3;
}

// --------------------------- conv worker ------------------------------------
// One (row, channel) item: sliding-window conv k=12 + relu + maxpool4,
// fully unrolled so the window shift is register renaming, not MOVs.
// __noinline__ so both call rounds share one code copy (I-cache).
__device__ __noinline__ void conv_item(const float* __restrict__ prs,
                                       float* __restrict__ featT,
                                       const float* __restrict__ s_convw,
                                       const float* __restrict__ s_convb,
                                       int item, int rowbase)
{
    int rl = item / NCH;
    int ch = item - rl * NCH;
    int rloc = rowbase + rl;
    float wr[CONVK];
    #pragma unroll
    for (int i = 0; i < CONVK; i++) wr[i] = s_convw[ch * CONVK + i];
    float bb = s_convb[ch];
    const float* prow = &prs[rl * 132];
    float* fp = &featT[ch * POOLN * 132 + rloc];
    float x[15];
    #pragma unroll
    for (int i = 0; i < 15; i++) x[i] = prow[i];
    #pragma unroll
    for (int p = 0; p < POOLN; p++) {
        float m = 0.f;                  // relu >= 0
        #pragma unroll
        for (int j = 0; j < 4; j++) {
            float acc = bb;
            #pragma unroll
            for (int tt = 0; tt < CONVK; tt++)
                acc = fmaf(x[j + tt], wr[tt], acc);
            m = fmaxf(m, acc);
        }
        fp[p * 132] = m;
        if (p < POOLN - 1) {
            #pragma unroll
            for (int i = 0; i < 11; i++) x[i] = x[i + 4];
            #pragma unroll
            for (int i = 0; i < 4; i++) x[11 + i] = prow[4 * p + 15 + i];
        }
    }
}

// ------------------------------ main kernel ---------------------------------
__global__ __launch_bounds__(THR, 1)
void main_kernel(const float* __restrict__ pr,
                 const void*  __restrict__ mask,
                 const float* __restrict__ conv_w,
                 const float* __restrict__ conv_b,
                 const float* __restrict__ cb,
                 float* __restrict__ out)
{
    extern __shared__ float sm[];
    float* featT    = sm;                       // [290][132]; later mu_t + partials
    float* regA     = sm + OFF_REGA;            // prs | wbuf (2 buf x 2 grp) | Ct
    float* s_convw  = sm + OFF_MISC;            // 120
    float* s_convb  = s_convw + 120;            // 12
    float* s_bf     = s_convb + 12;             // 128
    float* s_cnorm  = s_bf + 128;               // 64
    float* s_red    = s_cnorm + 64;             // 32
    int*   s_idx    = (int*)(s_red + 32);       // 128
    int*   s_counts = s_idx + 128;              // 64

    const int t   = threadIdx.x;
    const int blk = blockIdx.x;

    // ---- misc loads ----
    for (int i = t; i < 120; i += THR) s_convw[i] = conv_w[i];
    if (t < NCH)  s_convb[t] = conv_b[t];
    if (t < ZD)   s_bf[t]    = g_bf[t];
    if (t < KC_) { s_cnorm[t] = g_cnorm[t]; s_counts[t] = 0; }

    // =============== Phase 1: conv + relu + maxpool -> featT ===============
    float* prs = regA;                          // [64][132]
    for (int sub = 0; sub < 2; sub++) {
        int row0 = blk * ROWS + sub * 64;
        __syncthreads();                        // prs reuse / misc ready
        const float4* src = (const float4*)(pr + (size_t)row0 * LEN);
        for (int i = t; i < 64 * 32; i += THR) {
            int rr = i >> 5, c4 = i & 31;
            *(float4*)&prs[rr * 132 + c4 * 4] = src[i];
        }
        __syncthreads();
        // 640 items: every thread does item t; t<128 also item t+512
        conv_item(prs, featT, s_convw, s_convb, t, sub * 64);
        if (t < 128) conv_item(prs, featT, s_convw, s_convb, t + THR, sub * 64);
    }
    __syncthreads();                            // featT complete, prs dead

    // =============== Phase 2: mu = featT^T @ W + b, K-split x2 =============
    // group g handles chunks g*5 .. g*5+4 (each 29 k-steps), 8x8 tile/thread.
    const int g  = t >> 8;                      // 0 / 1
    const int tg = t & 255;
    const int r0 = (tg >> 4) * 8;
    const int j0 = (tg & 15) * 8;
    float acc[64];
    #pragma unroll
    for (int i = 0; i < 64; i++) acc[i] = 0.f;

    const float4* gW4 = (const float4*)g_W;
    float4 wpre[4];

    // load chunk pair 0 into buffer 0 (one exposed L2 latency per block)
    #pragma unroll
    for (int u = 0; u < 4; u++) {
        int i = t + u * THR;
        if (i < 1856) {
            int grp = i / 928, j = i - grp * 928;
            wpre[u] = gW4[(grp * NPHASE + 0) * 928 + j];
        }
    }
    #pragma unroll
    for (int u = 0; u < 4; u++) {
        int i = t + u * THR;
        if (i < 1856) {
            int grp = i / 928, j = i - grp * 928;
            *(float4*)&regA[grp * CHF + j * 4] = wpre[u];
        }
    }
    __syncthreads();

    for (int p = 0; p < NPHASE; p++) {
        // prefetch next chunk pair into regs (latency hidden by compute)
        if (p < NPHASE - 1) {
            #pragma unroll
            for (int u = 0; u < 4; u++) {
                int i = t + u * THR;
                if (i < 1856) {
                    int grp = i / 928, j = i - grp * 928;
                    wpre[u] = gW4[(grp * NPHASE + p + 1) * 928 + j];
                }
            }
        }
        const float* wb = regA + (p & 1) * (2 * CHF) + g * CHF;
        const int krow0 = (g * NPHASE + p) * KCH;
        #pragma unroll 4
        for (int kc = 0; kc < KCH; kc++) {
            const float* fa = &featT[(krow0 + kc) * 132 + r0];
            float4 a0 = *(const float4*)(fa);
            float4 a1 = *(const float4*)(fa + 4);
            const float* fb = &wb[kc * ZD + j0];
            float4 b0 = *(const float4*)(fb);
            float4 b1 = *(const float4*)(fb + 4);
            float av[8] = {a0.x, a0.y, a0.z, a0.w, a1.x, a1.y, a1.z, a1.w};
            float bv[8] = {b0.x, b0.y, b0.z, b0.w, b1.x, b1.y, b1.z, b1.w};
            #pragma unroll
            for (int ii = 0; ii < 8; ii++)
                #pragma unroll
                for (int jj = 0; jj < 8; jj++)
                    acc[ii * 8 + jj] = fmaf(av[ii], bv[jj], acc[ii * 8 + jj]);
        }
        if (p < NPHASE - 1) {
            #pragma unroll
            for (int u = 0; u < 4; u++) {
                int i = t + u * THR;
                if (i < 1856) {
                    int grp = i / 928, j = i - grp * 928;
                    *(float4*)&regA[((p + 1) & 1) * (2 * CHF) + grp * CHF + j * 4] = wpre[u];
                }
            }
        }
        __syncthreads();
    }

    // ---- merge K-split partials; write mu transposed; load Ct ----
    float* part = featT + PART_OFF;             // 256*64 floats
    float* mu_t = featT;                        // [128][132]
    float* Ct   = regA;                         // [128][68]
    if (g == 1) {
        float4* pp = (float4*)(part + tg * 64);
        #pragma unroll
        for (int i = 0; i < 16; i++)
            pp[i] = make_float4(acc[4*i], acc[4*i+1], acc[4*i+2], acc[4*i+3]);
    }
    __syncthreads();
    if (g == 0) {
        const float* pp = part + tg * 64;
        #pragma unroll
        for (int i = 0; i < 64; i++) acc[i] += pp[i];
        #pragma unroll
        for (int jj = 0; jj < 8; jj++) {
            float b = s_bf[j0 + jj];
            float* mrow = &mu_t[(j0 + jj) * 132 + r0];
            *(float4*)(mrow)     = make_float4(acc[0*8+jj]+b, acc[1*8+jj]+b,
                                               acc[2*8+jj]+b, acc[3*8+jj]+b);
            *(float4*)(mrow + 4) = make_float4(acc[4*8+jj]+b, acc[5*8+jj]+b,
                                               acc[6*8+jj]+b, acc[7*8+jj]+b);
        }
    } else {
        // group 1 loads codebook transposed: Ct[z][c], stride 68
        for (int i = tg; i < KC_ * ZD; i += 256) {
            int c = i >> 7, z = i & 127;
            Ct[z * 68 + c] = cb[i];
        }
    }
    __syncthreads();

    // =============== Phase 3: scores = mu @ C^T + argmin ===================
    {
        const int ty3 = t >> 4, tx3 = t & 15;
        const int rr0 = ty3 * 4, c0 = tx3 * 4;   // 4 rows x 4 codes per thread
        float sacc[16];
        #pragma unroll
        for (int i = 0; i < 16; i++) sacc[i] = 0.f;
        #pragma unroll 4
        for (int z = 0; z < ZD; z++) {
            float4 m = *(const float4*)&mu_t[z * 132 + rr0];
            float4 c = *(const float4*)&Ct[z * 68 + c0];
            float mv[4] = {m.x, m.y, m.z, m.w};
            float cv[4] = {c.x, c.y, c.z, c.w};
            #pragma unroll
            for (int ii = 0; ii < 4; ii++)
                #pragma unroll
                for (int jj = 0; jj < 4; jj++)
                    sacc[ii * 4 + jj] = fmaf(mv[ii], cv[jj], sacc[ii * 4 + jj]);
        }
        #pragma unroll
        for (int ii = 0; ii < 4; ii++) {
            float bv = 3.4e38f; int bi = 0;
            #pragma unroll
            for (int jj = 0; jj < 4; jj++) {
                float kv = s_cnorm[c0 + jj] - 2.f * sacc[ii * 4 + jj];
                if (kv < bv) { bv = kv; bi = c0 + jj; }
            }
            #pragma unroll
            for (int o = 1; o < 16; o <<= 1) {
                float ov = __shfl_xor_sync(0xffffffffu, bv, o);
                int   oi = __shfl_xor_sync(0xffffffffu, bi, o);
                if (ov < bv || (ov == bv && oi < bi)) { bv = ov; bi = oi; }
            }
            if (tx3 == 0) s_idx[rr0 + ii] = bi;
        }
    }
    __syncthreads();

    // =============== Phase 4: commitment, counts, z output =================
    const int flag_u8 = g_mask_u8;
    float cs = 0.f;
    int validrow = 0;
    if (t < ROWS) {
        int rg = blk * ROWS + t;
        validrow = flag_u8 ? (((const unsigned char*)mask)[rg] == 0)
                           : (((const int*)mask)[rg] == 0);
        int myidx = s_idx[t];
        #pragma unroll 4
        for (int z = 0; z < ZD; z++) {
            float d = Ct[z * 68 + myidx] - mu_t[z * 132 + t];
            cs = fmaf(d, d, cs);
        }
        if (validrow) atomicAdd(&s_counts[myidx], 1);
    }
    float v = (t < ROWS && validrow) ? cs : 0.f;
    #pragma unroll
    for (int o = 16; o > 0; o >>= 1) v += __shfl_down_sync(0xffffffffu, v, o);
    if ((t & 31) == 0) s_red[t >> 5] = v;
    __syncthreads();
    if (t == 0) {
        float tot = 0.f;
        for (int w = 0; w < 16; w++) tot += s_red[w];
        atomicAdd(&g_csum, tot);
    }
    if (t < KC_ && s_counts[t]) atomicAdd(&g_counts[t], s_counts[t]);

    // z = codebook[idx]
    long base = (long)blk * (ROWS * ZD);
    for (int i = t; i < ROWS * ZD; i += THR) {
        int r = i >> 7, z = i & 127;
        out[base + i] = cb[s_idx[r] * ZD + z];
    }
}

// ------------------------------ finalize ------------------------------------
__global__ void final_kernel(float* __restrict__ out)
{
    if (threadIdx.x == 0) {
        int nvi = 0;
        for (int k = 0; k < KC_; k++) nvi += g_counts[k];
        float nv = fmaxf((float)nvi, 1.f);
        float H = 0.f;
        for (int k = 0; k < KC_; k++) {
            float p = (float)g_counts[k] / nv;
            H += p * logf(p + 1e-10f);
        }
        out[(long)BS * ZD]     = 0.25f * g_csum / (nv * (float)ZD);
        out[(long)BS * ZD + 1] = expf(-H);
    }
}

// ------------------------------- launcher -----------------------------------
extern "C" void kernel_launch(void* const* d_in, const int* in_sizes, int n_in,
                              void* d_out, int out_size)
{
    const float* pr      = (const float*)d_in[0];
    const void*  mask    = d_in[1];
    const float* conv_w  = (const float*)d_in[2];
    const float* conv_b  = (const float*)d_in[3];
    const float* fc_w    = (const float*)d_in[4];
    const float* fc_b    = (const float*)d_in[5];
    const float* mu_w    = (const float*)d_in[6];
    const float* mu_b    = (const float*)d_in[7];
    const float* cb      = (const float*)d_in[8];
    float* out = (float*)d_out;

    cudaFuncSetAttribute(main_kernel,
                         cudaFuncAttributeMaxDynamicSharedMemorySize, SMEM_BYTES);

    setup_kernel<<<1, 256>>>(fc_b, mu_w, mu_b, cb);
    detect_kernel<<<(BS + 255) / 256, 256>>>((const unsigned char*)mask, BS);
    wfuse_kernel<<<(FEATN + 3) / 4, 128>>>(fc_w, mu_w);
    main_kernel<<<NBLK, THR, SMEM_BYTES>>>(pr, mask, conv_w, conv_b, cb, out);
    final_kernel<<<1, 32>>>(out);
}